// round 4
// baseline (speedup 1.0000x reference)
#include <cuda_runtime.h>
#include <cuda_bf16.h>
#include <cstdint>
#include <cstdio>

#define L_SEQ 512
#define NB    64
#define HID   1024
#define EMB   512

// ---------------- device scratch (no allocs allowed) ----------------
// xproj[t][n][g*1024+j] = bias_g[j] + x_emb(t,n) @ Wg[1024:1536, j]   (512 MB)
__device__ float g_xproj[(size_t)L_SEQ * NB * 4 * HID];
// h ping-pong, layout [hidden][batch]
__device__ float g_h[2 * HID * NB];
// c state, layout [hidden][batch]
__device__ float g_c[HID * NB];

// ---------------- packed fp32x2 helpers (FFMA2 on sm_103a) ----------------
__device__ __forceinline__ unsigned long long pk2(float a, float b) {
    unsigned long long r;
    asm("mov.b64 %0, {%1, %2};" : "=l"(r) : "f"(a), "f"(b));
    return r;
}
__device__ __forceinline__ void up2(unsigned long long v, float& lo, float& hi) {
    asm("mov.b64 {%0, %1}, %2;" : "=f"(lo), "=f"(hi) : "l"(v));
}
__device__ __forceinline__ void fma2(unsigned long long& d,
                                     unsigned long long a, unsigned long long b) {
    asm("fma.rn.f32x2 %0, %1, %2, %0;" : "+l"(d) : "l"(a), "l"(b));
}

// ---------------- init: zero h0, c0 ----------------
__global__ void k_init() {
    int i = blockIdx.x * blockDim.x + threadIdx.x;
    if (i < HID * NB) {
        g_h[i] = 0.f;   // ping buffer 0 (read at t=0)
        g_c[i] = 0.f;
    }
}

// ---------------- kernel 1: embedding gather + input projection ----------------
// xproj[m][gcol] = b_g[j] + sum_k emb[x[m]][k] * Wg[1024+k][j]
// grid: (32, 512)  block: 256
// CTA tile: 64 rows (m) x 128 cols (within one gate).  K = 512, chunks of 32.
__global__ __launch_bounds__(256) void k_embed_proj(
    const int*   __restrict__ x,   const float* __restrict__ emb,
    const float* __restrict__ Wi,  const float* __restrict__ bi,
    const float* __restrict__ Wf,  const float* __restrict__ bf,
    const float* __restrict__ Wc,  const float* __restrict__ bc,
    const float* __restrict__ Wo,  const float* __restrict__ bo)
{
    const int KC = 32;
    __shared__ float a2[KC][132];    // emb tile, duplicated pairs: [k][2m],[k][2m+1]
    __shared__ float bsh[KC][128];   // W tile [k][c]

    int tid = threadIdx.x;
    int bx  = blockIdx.x;            // 0..31 -> gate, col tile
    int by  = blockIdx.y;            // 0..511 -> 64-row tile
    int g   = bx >> 3;
    int jb  = (bx & 7) * 128;

    const float* Wg = (g == 0) ? Wi : (g == 1) ? Wf : (g == 2) ? Wc : Wo;
    const float* bg = (g == 0) ? bi : (g == 1) ? bf : (g == 2) ? bc : bo;

    // A (gather) load mapping: 4 threads per row, 8 floats each
    int arow  = tid & 63;
    int ahalf = tid >> 6;            // 0..3 -> k offset ahalf*8
    long tok  = x[by * 64 + arow];
    const float* erow = emb + (size_t)tok * EMB + ahalf * 8;

    // B load mapping: 8 threads per k-row, 16 floats each
    int bkk = tid >> 3;              // 0..31
    int bq  = tid & 7;               // 0..7
    const float* wrow = Wg + (size_t)(HID + bkk) * HID + jb + bq * 16;

    // compute mapping: thread tile = 4 m x 8 cols (4 col-pairs per m)
    int mg = tid >> 4;               // 0..15 -> m = mg*4
    int cg = tid & 15;               // 0..15 -> cols cg*8

    unsigned long long a00, a01, a02, a03, a10, a11, a12, a13;
    unsigned long long a20, a21, a22, a23, a30, a31, a32, a33;
    {
        float4 b0 = *(const float4*)(bg + jb + cg * 8);
        float4 b1 = *(const float4*)(bg + jb + cg * 8 + 4);
        unsigned long long i0 = pk2(b0.x, b0.y), i1 = pk2(b0.z, b0.w);
        unsigned long long i2 = pk2(b1.x, b1.y), i3 = pk2(b1.z, b1.w);
        a00 = i0; a01 = i1; a02 = i2; a03 = i3;
        a10 = i0; a11 = i1; a12 = i2; a13 = i3;
        a20 = i0; a21 = i1; a22 = i2; a23 = i3;
        a30 = i0; a31 = i1; a32 = i2; a33 = i3;
    }

    for (int kb = 0; kb < EMB; kb += KC) {
        // load A (gathered emb rows), store duplicated pairs
        float4 va0 = *(const float4*)(erow + kb);
        float4 va1 = *(const float4*)(erow + kb + 4);
        int k0 = ahalf * 8;
        *(float2*)&a2[k0 + 0][2 * arow] = make_float2(va0.x, va0.x);
        *(float2*)&a2[k0 + 1][2 * arow] = make_float2(va0.y, va0.y);
        *(float2*)&a2[k0 + 2][2 * arow] = make_float2(va0.z, va0.z);
        *(float2*)&a2[k0 + 3][2 * arow] = make_float2(va0.w, va0.w);
        *(float2*)&a2[k0 + 4][2 * arow] = make_float2(va1.x, va1.x);
        *(float2*)&a2[k0 + 5][2 * arow] = make_float2(va1.y, va1.y);
        *(float2*)&a2[k0 + 6][2 * arow] = make_float2(va1.z, va1.z);
        *(float2*)&a2[k0 + 7][2 * arow] = make_float2(va1.w, va1.w);
        // load B
        const float* wp = wrow + (size_t)kb * HID;
        *(float4*)&bsh[bkk][bq * 16 + 0]  = *(const float4*)(wp + 0);
        *(float4*)&bsh[bkk][bq * 16 + 4]  = *(const float4*)(wp + 4);
        *(float4*)&bsh[bkk][bq * 16 + 8]  = *(const float4*)(wp + 8);
        *(float4*)&bsh[bkk][bq * 16 + 12] = *(const float4*)(wp + 12);
        __syncthreads();
#pragma unroll
        for (int k = 0; k < KC; k++) {
            ulonglong2 aa0 = *(const ulonglong2*)&a2[k][8 * mg];      // (m0,m0),(m1,m1)
            ulonglong2 aa1 = *(const ulonglong2*)&a2[k][8 * mg + 4];  // (m2,m2),(m3,m3)
            ulonglong2 bb0 = *(const ulonglong2*)&bsh[k][cg * 8];     // col pairs 0,1
            ulonglong2 bb1 = *(const ulonglong2*)&bsh[k][cg * 8 + 4]; // col pairs 2,3
            fma2(a00, aa0.x, bb0.x); fma2(a01, aa0.x, bb0.y);
            fma2(a02, aa0.x, bb1.x); fma2(a03, aa0.x, bb1.y);
            fma2(a10, aa0.y, bb0.x); fma2(a11, aa0.y, bb0.y);
            fma2(a12, aa0.y, bb1.x); fma2(a13, aa0.y, bb1.y);
            fma2(a20, aa1.x, bb0.x); fma2(a21, aa1.x, bb0.y);
            fma2(a22, aa1.x, bb1.x); fma2(a23, aa1.x, bb1.y);
            fma2(a30, aa1.y, bb0.x); fma2(a31, aa1.y, bb0.y);
            fma2(a32, aa1.y, bb1.x); fma2(a33, aa1.y, bb1.y);
        }
        __syncthreads();
    }

    float* op = g_xproj + ((size_t)(by * 64 + mg * 4)) * 4096 + (size_t)g * 1024 + jb + cg * 8;
    float l0, h0, l1, h1, l2, h2, l3, h3;
#define ST_ROW(A0,A1,A2,A3,OFF)                                                  \
    up2(A0,l0,h0); up2(A1,l1,h1); up2(A2,l2,h2); up2(A3,l3,h3);                  \
    *(float4*)(op + (OFF))     = make_float4(l0, h0, l1, h1);                    \
    *(float4*)(op + (OFF) + 4) = make_float4(l2, h2, l3, h3);
    ST_ROW(a00, a01, a02, a03, 0);
    ST_ROW(a10, a11, a12, a13, 4096);
    ST_ROW(a20, a21, a22, a23, 8192);
    ST_ROW(a30, a31, a32, a33, 12288);
#undef ST_ROW
}

// ---------------- kernel 2: one LSTM timestep ----------------
// grid: 128 CTAs (each owns 8 hidden units, all 4 gates), block: 128 threads
// GEMM: preact[64 x 32] = h(64x1024) @ Wh-slices, acc init = xproj(+bias)
__global__ __launch_bounds__(128) void k_step(
    int t,
    const float* __restrict__ Wi, const float* __restrict__ Wf,
    const float* __restrict__ Wc, const float* __restrict__ Wo,
    float* __restrict__ out)
{
    const int KC = 32;
    __shared__ float ash[KC][68];    // h tile [k][m]
    __shared__ float w2[KC][68];     // W tile duplicated: col c at [k][2c],[k][2c+1]
    __shared__ float ps[64][36];     // preact [m][c]  (c = g*8 + jl)

    int tid = threadIdx.x;
    int j0  = blockIdx.x * 8;        // hidden units j0..j0+7

    const float* hprev = g_h + (size_t)(t & 1) * (HID * NB);
    float*       hnext = g_h + (size_t)((t + 1) & 1) * (HID * NB);

    // W load mapping: one gate per 32-thread group
    int wg  = tid >> 5;              // 0..3 (gate)
    int wkk = tid & 31;              // k within chunk
    const float* Wgp = (wg == 0) ? Wi : (wg == 1) ? Wf : (wg == 2) ? Wc : Wo;
    const float* wrow = Wgp + (size_t)wkk * HID + j0;

    // h load mapping: 4 threads per k-row, 16 floats each
    int hk = tid >> 2;               // 0..31
    int hq = tid & 3;                // 0..3

    // compute mapping: thread tile = 4 m (2 pairs) x 4 cols
    int mg = tid >> 3;               // 0..15 -> m = mg*4
    int cg = tid & 7;                // 0..7  -> cols cg*4

    unsigned long long c00, c01, c02, c03, c10, c11, c12, c13;
    {
        // init accumulators from xproj (bias already folded in)
        int gg   = cg >> 1;
        int xcol = gg * 1024 + j0 + (cg & 1) * 4;
        const float* xp = g_xproj + ((size_t)t * 64 + mg * 4) * 4096 + xcol;
        float4 v0 = *(const float4*)(xp);
        float4 v1 = *(const float4*)(xp + 4096);
        float4 v2 = *(const float4*)(xp + 8192);
        float4 v3 = *(const float4*)(xp + 12288);
        c00 = pk2(v0.x, v1.x); c01 = pk2(v0.y, v1.y);
        c02 = pk2(v0.z, v1.z); c03 = pk2(v0.w, v1.w);
        c10 = pk2(v2.x, v3.x); c11 = pk2(v2.y, v3.y);
        c12 = pk2(v2.z, v3.z); c13 = pk2(v2.w, v3.w);
    }

    for (int kb = 0; kb < HID; kb += KC) {
        // load h tile (coalesced, [k][m] layout)
        const float* hp = hprev + (size_t)(kb + hk) * 64 + hq * 16;
        float4 h0 = *(const float4*)(hp + 0);
        float4 h1 = *(const float4*)(hp + 4);
        float4 h2 = *(const float4*)(hp + 8);
        float4 h3 = *(const float4*)(hp + 12);
        *(float4*)&ash[hk][hq * 16 + 0]  = h0;
        *(float4*)&ash[hk][hq * 16 + 4]  = h1;
        *(float4*)&ash[hk][hq * 16 + 8]  = h2;
        *(float4*)&ash[hk][hq * 16 + 12] = h3;
        // load W slice (8 cols of one gate), store duplicated pairs
        const float* wp = wrow + (size_t)kb * HID;
        float4 wv0 = *(const float4*)(wp + 0);
        float4 wv1 = *(const float4*)(wp + 4);
        int c2 = wg * 16;
        *(float2*)&w2[wkk][c2 + 0]  = make_float2(wv0.x, wv0.x);
        *(float2*)&w2[wkk][c2 + 2]  = make_float2(wv0.y, wv0.y);
        *(float2*)&w2[wkk][c2 + 4]  = make_float2(wv0.z, wv0.z);
        *(float2*)&w2[wkk][c2 + 6]  = make_float2(wv0.w, wv0.w);
        *(float2*)&w2[wkk][c2 + 8]  = make_float2(wv1.x, wv1.x);
        *(float2*)&w2[wkk][c2 + 10] = make_float2(wv1.y, wv1.y);
        *(float2*)&w2[wkk][c2 + 12] = make_float2(wv1.z, wv1.z);
        *(float2*)&w2[wkk][c2 + 14] = make_float2(wv1.w, wv1.w);
        __syncthreads();
#pragma unroll
        for (int k = 0; k < KC; k++) {
            ulonglong2 aa  = *(const ulonglong2*)&ash[k][mg * 4];     // (m0,m1),(m2,m3)
            ulonglong2 bb0 = *(const ulonglong2*)&w2[k][cg * 8];      // (c0,c0),(c1,c1)
            ulonglong2 bb1 = *(const ulonglong2*)&w2[k][cg * 8 + 4];  // (c2,c2),(c3,c3)
            fma2(c00, aa.x, bb0.x); fma2(c01, aa.x, bb0.y);
            fma2(c02, aa.x, bb1.x); fma2(c03, aa.x, bb1.y);
            fma2(c10, aa.y, bb0.x); fma2(c11, aa.y, bb0.y);
            fma2(c12, aa.y, bb1.x); fma2(c13, aa.y, bb1.y);
        }
        __syncthreads();
    }

    // preact -> smem
    {
        float p0a, p0b, p1a, p1b, p2a, p2b, p3a, p3b;
        up2(c00, p0a, p0b); up2(c01, p1a, p1b); up2(c02, p2a, p2b); up2(c03, p3a, p3b);
        *(float4*)&ps[mg * 4 + 0][cg * 4] = make_float4(p0a, p1a, p2a, p3a);
        *(float4*)&ps[mg * 4 + 1][cg * 4] = make_float4(p0b, p1b, p2b, p3b);
        up2(c10, p0a, p0b); up2(c11, p1a, p1b); up2(c12, p2a, p2b); up2(c13, p3a, p3b);
        *(float4*)&ps[mg * 4 + 2][cg * 4] = make_float4(p0a, p1a, p2a, p3a);
        *(float4*)&ps[mg * 4 + 3][cg * 4] = make_float4(p0b, p1b, p2b, p3b);
    }
    __syncthreads();

    // elementwise gates: thread -> one hidden unit (jl), 4 batch rows
    int jl  = tid & 7;
    int ms  = (tid >> 3) * 4;
    int j   = j0 + jl;
    float4 cold = *(float4*)&g_c[(size_t)j * 64 + ms];
    float cv[4] = {cold.x, cold.y, cold.z, cold.w};
    float hv[4];
#pragma unroll
    for (int q = 0; q < 4; q++) {
        int m = ms + q;
        float iv = ps[m][jl];
        float fv = ps[m][8 + jl];
        float gv = ps[m][16 + jl];
        float ov = ps[m][24 + jl];
        float is = 1.f / (1.f + __expf(-iv));
        float fs = 1.f / (1.f + __expf(-fv));
        float os = 1.f / (1.f + __expf(-ov));
        float gt = tanhf(gv);
        float cn = fs * cv[q] + is * gt;
        cv[q] = cn;
        hv[q] = os * tanhf(cn);
    }
    *(float4*)&g_c[(size_t)j * 64 + ms]   = make_float4(cv[0], cv[1], cv[2], cv[3]);
    *(float4*)&hnext[(size_t)j * 64 + ms] = make_float4(hv[0], hv[1], hv[2], hv[3]);
    float* op = out + ((size_t)t * 64 + ms) * 1024 + j;
    op[0]    = hv[0];
    op[1024] = hv[1];
    op[2048] = hv[2];
    op[3072] = hv[3];
}

// ---------------- launcher ----------------
extern "C" void kernel_launch(void* const* d_in, const int* in_sizes, int n_in,
                              void* d_out, int out_size)
{
    const int*   x   = (const int*)  d_in[0];
    const float* emb = (const float*)d_in[1];
    const float* Wi  = (const float*)d_in[2];
    const float* bi  = (const float*)d_in[3];
    const float* Wf  = (const float*)d_in[4];
    const float* bf  = (const float*)d_in[5];
    const float* Wc  = (const float*)d_in[6];
    const float* bc  = (const float*)d_in[7];
    const float* Wo  = (const float*)d_in[8];
    const float* bo  = (const float*)d_in[9];
    float* out = (float*)d_out;

    (void)in_sizes; (void)n_in; (void)out_size;

    k_init<<<(HID * NB + 255) / 256, 256>>>();

    dim3 g1(32, 512);
    k_embed_proj<<<g1, 256>>>(x, emb, Wi, bi, Wf, bf, Wc, bc, Wo, bo);

    for (int t = 0; t < L_SEQ; t++) {
        k_step<<<128, 128>>>(t, Wi, Wf, Wc, Wo, out);
    }
}

// round 5
// speedup vs baseline: 1.8017x; 1.8017x over previous
#include <cuda_runtime.h>
#include <cstdint>

#define L_SEQ 512
#define NB    64
#define HID   1024
#define EMB   512
#define NC    4096   // 4 gates * HID, interleaved col = j*4 + g  (g: 0=i,1=f,2=c,3=o)

typedef unsigned long long ull;

// ---------------- device scratch (no allocs allowed) ----------------
__device__ float g_xproj[(size_t)L_SEQ * NB * NC];     // 512 MB: bias + x-part preacts
__device__ float g_Wr[(size_t)(HID + EMB) * NC];       // 25 MB: interleaved weights
__device__ float g_br[NC];                             // interleaved bias
__device__ float g_h[2 * HID * NB];                    // ping-pong, layout [j][m]
__device__ float g_c[HID * NB];                        // layout [j][m]

// ---------------- packed fp32x2 helpers (FFMA2 on sm_103a) ----------------
__device__ __forceinline__ ull pk2(float a, float b) {
    ull r; asm("mov.b64 %0, {%1, %2};" : "=l"(r) : "f"(a), "f"(b)); return r;
}
__device__ __forceinline__ void up2(ull v, float& lo, float& hi) {
    asm("mov.b64 {%0, %1}, %2;" : "=f"(lo), "=f"(hi) : "l"(v));
}
__device__ __forceinline__ void fma2(ull& d, ull a, ull b) {
    asm("fma.rn.f32x2 %0, %1, %2, %0;" : "+l"(d) : "l"(a), "l"(b));
}
__device__ __forceinline__ ull add2(ull a, ull b) {
    ull r; asm("add.rn.f32x2 %0, %1, %2;" : "=l"(r) : "l"(a), "l"(b)); return r;
}

// ---------------- init: zero h0 (ping 0), c0 ----------------
__global__ void k_init() {
    int i = blockIdx.x * blockDim.x + threadIdx.x;
    if (i < HID * NB) { g_h[i] = 0.f; g_c[i] = 0.f; }
}

// ---------------- weight/bias reorg: col = j*4 + g ----------------
__global__ void k_reorg(const float* __restrict__ Wi, const float* __restrict__ bi,
                        const float* __restrict__ Wf, const float* __restrict__ bf,
                        const float* __restrict__ Wc, const float* __restrict__ bc,
                        const float* __restrict__ Wo, const float* __restrict__ bo) {
    int idx = blockIdx.x * 256 + threadIdx.x;
    if (idx < (HID + EMB) * HID) {
        int k = idx >> 10, j = idx & (HID - 1);
        size_t s = (size_t)k * HID + j;
        float4 v = make_float4(Wi[s], Wf[s], Wc[s], Wo[s]);
        *(float4*)&g_Wr[(size_t)k * NC + j * 4] = v;
    }
    if (idx < HID) {
        *(float4*)&g_br[idx * 4] = make_float4(bi[idx], bf[idx], bc[idx], bo[idx]);
    }
}

// ---------------- kernel 1: embedding gather + input projection ----------------
// xproj[m][c] = br[c] + sum_k emb[x[m]][k] * Wr[1024+k][c]
// grid: (32, 512) block 256.  CTA tile: 64 rows x 128 interleaved cols, K=512.
__global__ __launch_bounds__(256) void k_embed_proj(
    const int* __restrict__ x, const float* __restrict__ emb)
{
    const int KC = 32;
    __shared__ float a2[KC][132];    // emb tile, duplicated pairs
    __shared__ float bsh[KC][128];   // W tile [k][c]

    int tid = threadIdx.x;
    int jb  = blockIdx.x * 128;      // col tile base (interleaved space)
    int by  = blockIdx.y;            // 64-row tile

    int arow  = tid & 63;
    int ahalf = tid >> 6;
    long tok  = x[by * 64 + arow];
    const float* erow = emb + (size_t)tok * EMB + ahalf * 8;

    int bkk = tid >> 3;
    int bq  = tid & 7;
    const float* wrow = g_Wr + (size_t)(HID + bkk) * NC + jb + bq * 16;

    int mg = tid >> 4;
    int cg = tid & 15;

    ull a00, a01, a02, a03, a10, a11, a12, a13;
    ull a20, a21, a22, a23, a30, a31, a32, a33;
    {
        float4 b0 = *(const float4*)(g_br + jb + cg * 8);
        float4 b1 = *(const float4*)(g_br + jb + cg * 8 + 4);
        ull i0 = pk2(b0.x, b0.y), i1 = pk2(b0.z, b0.w);
        ull i2 = pk2(b1.x, b1.y), i3 = pk2(b1.z, b1.w);
        a00 = i0; a01 = i1; a02 = i2; a03 = i3;
        a10 = i0; a11 = i1; a12 = i2; a13 = i3;
        a20 = i0; a21 = i1; a22 = i2; a23 = i3;
        a30 = i0; a31 = i1; a32 = i2; a33 = i3;
    }

    for (int kb = 0; kb < EMB; kb += KC) {
        float4 va0 = *(const float4*)(erow + kb);
        float4 va1 = *(const float4*)(erow + kb + 4);
        int k0 = ahalf * 8;
        *(float2*)&a2[k0 + 0][2 * arow] = make_float2(va0.x, va0.x);
        *(float2*)&a2[k0 + 1][2 * arow] = make_float2(va0.y, va0.y);
        *(float2*)&a2[k0 + 2][2 * arow] = make_float2(va0.z, va0.z);
        *(float2*)&a2[k0 + 3][2 * arow] = make_float2(va0.w, va0.w);
        *(float2*)&a2[k0 + 4][2 * arow] = make_float2(va1.x, va1.x);
        *(float2*)&a2[k0 + 5][2 * arow] = make_float2(va1.y, va1.y);
        *(float2*)&a2[k0 + 6][2 * arow] = make_float2(va1.z, va1.z);
        *(float2*)&a2[k0 + 7][2 * arow] = make_float2(va1.w, va1.w);
        const float* wp = wrow + (size_t)kb * NC;
        *(float4*)&bsh[bkk][bq * 16 + 0]  = *(const float4*)(wp + 0);
        *(float4*)&bsh[bkk][bq * 16 + 4]  = *(const float4*)(wp + 4);
        *(float4*)&bsh[bkk][bq * 16 + 8]  = *(const float4*)(wp + 8);
        *(float4*)&bsh[bkk][bq * 16 + 12] = *(const float4*)(wp + 12);
        __syncthreads();
#pragma unroll
        for (int k = 0; k < KC; k++) {
            ulonglong2 aa0 = *(const ulonglong2*)&a2[k][8 * mg];
            ulonglong2 aa1 = *(const ulonglong2*)&a2[k][8 * mg + 4];
            ulonglong2 bb0 = *(const ulonglong2*)&bsh[k][cg * 8];
            ulonglong2 bb1 = *(const ulonglong2*)&bsh[k][cg * 8 + 4];
            fma2(a00, aa0.x, bb0.x); fma2(a01, aa0.x, bb0.y);
            fma2(a02, aa0.x, bb1.x); fma2(a03, aa0.x, bb1.y);
            fma2(a10, aa0.y, bb0.x); fma2(a11, aa0.y, bb0.y);
            fma2(a12, aa0.y, bb1.x); fma2(a13, aa0.y, bb1.y);
            fma2(a20, aa1.x, bb0.x); fma2(a21, aa1.x, bb0.y);
            fma2(a22, aa1.x, bb1.x); fma2(a23, aa1.x, bb1.y);
            fma2(a30, aa1.y, bb0.x); fma2(a31, aa1.y, bb0.y);
            fma2(a32, aa1.y, bb1.x); fma2(a33, aa1.y, bb1.y);
        }
        __syncthreads();
    }

    float* op = g_xproj + ((size_t)(by * 64 + mg * 4)) * NC + jb + cg * 8;
    float l0, h0, l1, h1, l2, h2, l3, h3;
#define ST_ROW(A0,A1,A2,A3,OFF)                                                  \
    up2(A0,l0,h0); up2(A1,l1,h1); up2(A2,l2,h2); up2(A3,l3,h3);                  \
    *(float4*)(op + (OFF))     = make_float4(l0, h0, l1, h1);                    \
    *(float4*)(op + (OFF) + 4) = make_float4(l2, h2, l3, h3);
    ST_ROW(a00, a01, a02, a03, 0);
    ST_ROW(a10, a11, a12, a13, NC);
    ST_ROW(a20, a21, a22, a23, 2 * NC);
    ST_ROW(a30, a31, a32, a33, 3 * NC);
#undef ST_ROW
}

// ---------------- kernel 2: one LSTM timestep (GEMM + gates fused) ----------------
// grid: 256 CTAs x 256 threads. CTA owns 4 hidden units (16 interleaved cols), 64 batch.
// 8 warps = 2 M-halves x 4 K-quarters (split-K). Warp: 16 m-pairs x 16 cols, K=256.
// Thread: 4 m-pairs x 2 cols = 8 packed accumulators.
#define BSTRIDE 36
#define SM_FLOATS (8192 + 128 * BSTRIDE)   // ash 128x64 + bsh 128x36
#define SMEM_STEP (SM_FLOATS * 4)

__global__ __launch_bounds__(256) void k_step(int t, float* __restrict__ out)
{
    extern __shared__ float sm[];
    float* ash = sm;            // [row 0..127][64]   row = kg*32 + kk
    float* bsh = sm + 8192;     // [row 0..127][36]   cols duplicated (32 used)

    int tid  = threadIdx.x;
    int jb   = blockIdx.x * 4;      // hidden units jb..jb+3
    int C0   = jb * 4;              // interleaved col base (16 cols)
    const float* hprev = g_h + (size_t)(t & 1) * (HID * NB);
    float*       hnext = g_h + (size_t)((t + 1) & 1) * (HID * NB);

    int lane = tid & 31, wid = tid >> 5;
    int kg = wid & 3;               // k quarter
    int mh = wid >> 2;              // m half (pairs 16*mh..)
    int mi = lane >> 3;             // 0..3 -> 4 pairs each
    int ci = lane & 7;              // 0..7 -> cols 2ci, 2ci+1

    ull c0 = 0, c1 = 0, c2 = 0, c3 = 0, c4 = 0, c5 = 0, c6 = 0, c7 = 0;

    // register-prefetch staging
    float4 ra[8], rb[2];
#define LOAD_A(BASE)                                                             \
    _Pragma("unroll")                                                            \
    for (int i = 0; i < 8; i++) {                                                \
        int f = tid + i * 256; int row = f >> 4, pos = f & 15;                   \
        int krow = ((row >> 5) << 8) + (BASE) + (row & 31);                      \
        ra[i] = *(const float4*)&hprev[(size_t)krow * 64 + pos * 4];             \
    }
#define LOAD_B(BASE)                                                             \
    _Pragma("unroll")                                                            \
    for (int i = 0; i < 2; i++) {                                                \
        int f = tid + i * 256; int row = f >> 2, q = f & 3;                      \
        int krow = ((row >> 5) << 8) + (BASE) + (row & 31);                      \
        rb[i] = *(const float4*)&g_Wr[(size_t)krow * NC + C0 + q * 4];           \
    }

    LOAD_A(0)
    LOAD_B(0)

    for (int it = 0; it < 8; it++) {
        __syncthreads();
#pragma unroll
        for (int i = 0; i < 8; i++) {
            int f = tid + i * 256; int row = f >> 4, pos = f & 15;
            *(float4*)&ash[row * 64 + pos * 4] = ra[i];
        }
#pragma unroll
        for (int i = 0; i < 2; i++) {
            int f = tid + i * 256; int row = f >> 2, q = f & 3;
            float4 v = rb[i];
            float* bp = &bsh[row * BSTRIDE + q * 8];
            *(float2*)(bp + 0) = make_float2(v.x, v.x);
            *(float2*)(bp + 2) = make_float2(v.y, v.y);
            *(float2*)(bp + 4) = make_float2(v.z, v.z);
            *(float2*)(bp + 6) = make_float2(v.w, v.w);
        }
        __syncthreads();
        if (it < 7) {
            int base = (it + 1) * 32;
            LOAD_A(base)
            LOAD_B(base)
        }
        const float* ap = &ash[(kg * 32) * 64 + mh * 32 + mi * 8];
        const float* bp = &bsh[(kg * 32) * BSTRIDE + ci * 4];
#pragma unroll
        for (int kk = 0; kk < 32; kk++) {
            ulonglong2 a0 = *(const ulonglong2*)(ap + kk * 64);       // pairs p0,p1
            ulonglong2 a1 = *(const ulonglong2*)(ap + kk * 64 + 4);   // pairs p2,p3
            ulonglong2 b0 = *(const ulonglong2*)(bp + kk * BSTRIDE);  // (ce,ce),(co,co)
            fma2(c0, a0.x, b0.x); fma2(c1, a0.x, b0.y);
            fma2(c2, a0.y, b0.x); fma2(c3, a0.y, b0.y);
            fma2(c4, a1.x, b0.x); fma2(c5, a1.x, b0.y);
            fma2(c6, a1.y, b0.x); fma2(c7, a1.y, b0.y);
        }
    }
#undef LOAD_A
#undef LOAD_B

    // split-K partials -> smem (alias staging buffers)
    __syncthreads();
    ull* pu = (ull*)sm;   // [wid 8][pair 16][col 16]
    {
        int pb = wid * 256;
        pu[pb + (4 * mi + 0) * 16 + 2 * ci]     = c0;
        pu[pb + (4 * mi + 0) * 16 + 2 * ci + 1] = c1;
        pu[pb + (4 * mi + 1) * 16 + 2 * ci]     = c2;
        pu[pb + (4 * mi + 1) * 16 + 2 * ci + 1] = c3;
        pu[pb + (4 * mi + 2) * 16 + 2 * ci]     = c4;
        pu[pb + (4 * mi + 2) * 16 + 2 * ci + 1] = c5;
        pu[pb + (4 * mi + 3) * 16 + 2 * ci]     = c6;
        pu[pb + (4 * mi + 3) * 16 + 2 * ci + 1] = c7;
    }
    __syncthreads();

    // gates: thread -> (m, jl):  m = tid>>2, jl = tid&3
    int m  = tid >> 2;
    int jl = tid & 3;
    int P  = m >> 1, e = m & 1;
    int ph = P >> 4, pl = P & 15;

    float4 xp = *(const float4*)&g_xproj[((size_t)t * 64 + m) * NC + C0 + jl * 4];
    float pre[4];
#pragma unroll
    for (int g = 0; g < 4; g++) {
        int lc = jl * 4 + g;
        ull s = add2(add2(pu[(ph * 4 + 0) * 256 + pl * 16 + lc],
                          pu[(ph * 4 + 1) * 256 + pl * 16 + lc]),
                     add2(pu[(ph * 4 + 2) * 256 + pl * 16 + lc],
                          pu[(ph * 4 + 3) * 256 + pl * 16 + lc]));
        float lo, hi; up2(s, lo, hi);
        pre[g] = e ? hi : lo;
    }
    pre[0] += xp.x; pre[1] += xp.y; pre[2] += xp.z; pre[3] += xp.w;

    float is = 1.f / (1.f + __expf(-pre[0]));
    float fs = 1.f / (1.f + __expf(-pre[1]));
    float gt = tanhf(pre[2]);
    float os = 1.f / (1.f + __expf(-pre[3]));

    int j = jb + jl;
    float cold = g_c[(size_t)j * 64 + m];
    float cn   = fs * cold + is * gt;
    g_c[(size_t)j * 64 + m]   = cn;
    float hv = os * tanhf(cn);
    hnext[(size_t)j * 64 + m] = hv;
    out[((size_t)t * 64 + m) * 1024 + j] = hv;
}

// ---------------- launcher ----------------
extern "C" void kernel_launch(void* const* d_in, const int* in_sizes, int n_in,
                              void* d_out, int out_size)
{
    const int*   x   = (const int*)  d_in[0];
    const float* emb = (const float*)d_in[1];
    const float* Wi  = (const float*)d_in[2];
    const float* bi  = (const float*)d_in[3];
    const float* Wf  = (const float*)d_in[4];
    const float* bf  = (const float*)d_in[5];
    const float* Wc  = (const float*)d_in[6];
    const float* bc  = (const float*)d_in[7];
    const float* Wo  = (const float*)d_in[8];
    const float* bo  = (const float*)d_in[9];
    float* out = (float*)d_out;
    (void)in_sizes; (void)n_in; (void)out_size;

    static bool attr_done = false;
    if (!attr_done) {
        cudaFuncSetAttribute(k_step, cudaFuncAttributeMaxDynamicSharedMemorySize,
                             SMEM_STEP);
        attr_done = true;
    }

    k_init<<<(HID * NB + 255) / 256, 256>>>();
    k_reorg<<<((HID + EMB) * HID + 255) / 256, 256>>>(Wi, bi, Wf, bf, Wc, bc, Wo, bo);

    dim3 g1(32, 512);
    k_embed_proj<<<g1, 256>>>(x, emb);

    for (int t = 0; t < L_SEQ; t++) {
        k_step<<<256, 256, SMEM_STEP>>>(t, out);
    }
}

// round 6
// speedup vs baseline: 2.2893x; 1.2707x over previous
#include <cuda_runtime.h>
#include <cstdint>

#define L_SEQ 512
#define NB    64
#define HID   1024
#define EMB   512
#define NC    4096   // 4 gates * HID, interleaved col = j*4 + g  (g: 0=i,1=f,2=c,3=o)

typedef unsigned long long ull;

// ---------------- device scratch (no allocs allowed) ----------------
__device__ float g_xproj[(size_t)L_SEQ * NB * NC];     // 512 MB: bias + x-part preacts
__device__ float g_Wr[(size_t)(HID + EMB) * NC];       // 25 MB: interleaved weights
__device__ float g_br[NC];                             // interleaved bias
__device__ float g_h[2 * HID * NB];                    // ping-pong, layout [j][m]
__device__ float g_c[HID * NB];                        // layout [j][m]

// ---------------- packed fp32x2 helpers (FFMA2 on sm_103a) ----------------
__device__ __forceinline__ ull pk2(float a, float b) {
    ull r; asm("mov.b64 %0, {%1, %2};" : "=l"(r) : "f"(a), "f"(b)); return r;
}
__device__ __forceinline__ ull dup2(float v) {
    ull r; asm("mov.b64 %0, {%1, %1};" : "=l"(r) : "f"(v)); return r;
}
__device__ __forceinline__ void up2(ull v, float& lo, float& hi) {
    asm("mov.b64 {%0, %1}, %2;" : "=f"(lo), "=f"(hi) : "l"(v));
}
__device__ __forceinline__ void fma2(ull& d, ull a, ull b) {
    asm("fma.rn.f32x2 %0, %1, %2, %0;" : "+l"(d) : "l"(a), "l"(b));
}
__device__ __forceinline__ ull add2(ull a, ull b) {
    ull r; asm("add.rn.f32x2 %0, %1, %2;" : "=l"(r) : "l"(a), "l"(b)); return r;
}

// ---------------- init: zero h0 (ping 0), c0 ----------------
__global__ void k_init() {
    int i = blockIdx.x * blockDim.x + threadIdx.x;
    if (i < HID * NB) { g_h[i] = 0.f; g_c[i] = 0.f; }
}

// ---------------- weight/bias reorg: col = j*4 + g ----------------
__global__ void k_reorg(const float* __restrict__ Wi, const float* __restrict__ bi,
                        const float* __restrict__ Wf, const float* __restrict__ bf,
                        const float* __restrict__ Wc, const float* __restrict__ bc,
                        const float* __restrict__ Wo, const float* __restrict__ bo) {
    int idx = blockIdx.x * 256 + threadIdx.x;
    if (idx < (HID + EMB) * HID) {
        int k = idx >> 10, j = idx & (HID - 1);
        size_t s = (size_t)k * HID + j;
        float4 v = make_float4(Wi[s], Wf[s], Wc[s], Wo[s]);
        *(float4*)&g_Wr[(size_t)k * NC + j * 4] = v;
    }
    if (idx < HID) {
        *(float4*)&g_br[idx * 4] = make_float4(bi[idx], bf[idx], bc[idx], bo[idx]);
    }
}

// ---------------- kernel 1: embedding gather + input projection ----------------
// xproj[m][c] = br[c] + sum_k emb[x[m]][k] * Wr[1024+k][c]
// grid: (32, 512) block 256.  CTA tile: 64 rows x 128 interleaved cols, K=512.
__global__ __launch_bounds__(256) void k_embed_proj(
    const int* __restrict__ x, const float* __restrict__ emb)
{
    const int KC = 32;
    __shared__ float a2[KC][132];    // emb tile, duplicated pairs
    __shared__ float bsh[KC][128];   // W tile [k][c]

    int tid = threadIdx.x;
    int jb  = blockIdx.x * 128;      // col tile base (interleaved space)
    int by  = blockIdx.y;            // 64-row tile

    int arow  = tid & 63;
    int ahalf = tid >> 6;
    long tok  = x[by * 64 + arow];
    const float* erow = emb + (size_t)tok * EMB + ahalf * 8;

    int bkk = tid >> 3;
    int bq  = tid & 7;
    const float* wrow = g_Wr + (size_t)(HID + bkk) * NC + jb + bq * 16;

    int mg = tid >> 4;
    int cg = tid & 15;

    ull a00, a01, a02, a03, a10, a11, a12, a13;
    ull a20, a21, a22, a23, a30, a31, a32, a33;
    {
        float4 b0 = *(const float4*)(g_br + jb + cg * 8);
        float4 b1 = *(const float4*)(g_br + jb + cg * 8 + 4);
        ull i0 = pk2(b0.x, b0.y), i1 = pk2(b0.z, b0.w);
        ull i2 = pk2(b1.x, b1.y), i3 = pk2(b1.z, b1.w);
        a00 = i0; a01 = i1; a02 = i2; a03 = i3;
        a10 = i0; a11 = i1; a12 = i2; a13 = i3;
        a20 = i0; a21 = i1; a22 = i2; a23 = i3;
        a30 = i0; a31 = i1; a32 = i2; a33 = i3;
    }

    for (int kb = 0; kb < EMB; kb += KC) {
        float4 va0 = *(const float4*)(erow + kb);
        float4 va1 = *(const float4*)(erow + kb + 4);
        int k0 = ahalf * 8;
        *(float2*)&a2[k0 + 0][2 * arow] = make_float2(va0.x, va0.x);
        *(float2*)&a2[k0 + 1][2 * arow] = make_float2(va0.y, va0.y);
        *(float2*)&a2[k0 + 2][2 * arow] = make_float2(va0.z, va0.z);
        *(float2*)&a2[k0 + 3][2 * arow] = make_float2(va0.w, va0.w);
        *(float2*)&a2[k0 + 4][2 * arow] = make_float2(va1.x, va1.x);
        *(float2*)&a2[k0 + 5][2 * arow] = make_float2(va1.y, va1.y);
        *(float2*)&a2[k0 + 6][2 * arow] = make_float2(va1.z, va1.z);
        *(float2*)&a2[k0 + 7][2 * arow] = make_float2(va1.w, va1.w);
        const float* wp = wrow + (size_t)kb * NC;
        *(float4*)&bsh[bkk][bq * 16 + 0]  = *(const float4*)(wp + 0);
        *(float4*)&bsh[bkk][bq * 16 + 4]  = *(const float4*)(wp + 4);
        *(float4*)&bsh[bkk][bq * 16 + 8]  = *(const float4*)(wp + 8);
        *(float4*)&bsh[bkk][bq * 16 + 12] = *(const float4*)(wp + 12);
        __syncthreads();
#pragma unroll
        for (int k = 0; k < KC; k++) {
            ulonglong2 aa0 = *(const ulonglong2*)&a2[k][8 * mg];
            ulonglong2 aa1 = *(const ulonglong2*)&a2[k][8 * mg + 4];
            ulonglong2 bb0 = *(const ulonglong2*)&bsh[k][cg * 8];
            ulonglong2 bb1 = *(const ulonglong2*)&bsh[k][cg * 8 + 4];
            fma2(a00, aa0.x, bb0.x); fma2(a01, aa0.x, bb0.y);
            fma2(a02, aa0.x, bb1.x); fma2(a03, aa0.x, bb1.y);
            fma2(a10, aa0.y, bb0.x); fma2(a11, aa0.y, bb0.y);
            fma2(a12, aa0.y, bb1.x); fma2(a13, aa0.y, bb1.y);
            fma2(a20, aa1.x, bb0.x); fma2(a21, aa1.x, bb0.y);
            fma2(a22, aa1.x, bb1.x); fma2(a23, aa1.x, bb1.y);
            fma2(a30, aa1.y, bb0.x); fma2(a31, aa1.y, bb0.y);
            fma2(a32, aa1.y, bb1.x); fma2(a33, aa1.y, bb1.y);
        }
        __syncthreads();
    }

    float* op = g_xproj + ((size_t)(by * 64 + mg * 4)) * NC + jb + cg * 8;
    float l0, h0, l1, h1, l2, h2, l3, h3;
#define ST_ROW(A0,A1,A2,A3,OFF)                                                  \
    up2(A0,l0,h0); up2(A1,l1,h1); up2(A2,l2,h2); up2(A3,l3,h3);                  \
    *(float4*)(op + (OFF))     = make_float4(l0, h0, l1, h1);                    \
    *(float4*)(op + (OFF) + 4) = make_float4(l2, h2, l3, h3);
    ST_ROW(a00, a01, a02, a03, 0);
    ST_ROW(a10, a11, a12, a13, NC);
    ST_ROW(a20, a21, a22, a23, 2 * NC);
    ST_ROW(a30, a31, a32, a33, 3 * NC);
#undef ST_ROW
}

// ---------------- kernel 2: one LSTM timestep (GEMM + gates fused) ----------------
// grid: 256 CTAs x 256 threads. CTA owns 4 hidden units (16 interleaved cols), 64 batch.
// 8 warps = 8-way split-K (K=128 each). Warp covers full 64 m x 16 cols.
// Thread: 4 m-pairs x 4 cols = 16 packed accumulators; per k: 3 LDS.128 + 16 FFMA2.
__global__ __launch_bounds__(256, 2) void k_step(int t, float* __restrict__ out)
{
    __shared__ float ash[128 * 64];     // [k-row within chunk][m]   32 KB
    __shared__ float bsh[128 * 16];     // [k-row within chunk][col] 8 KB

    int tid = threadIdx.x;
    int jb  = blockIdx.x * 4;           // hidden units jb..jb+3
    int C0  = jb * 4;                   // interleaved col base (16 cols)
    const float* hprev = g_h + (size_t)(t & 1) * (HID * NB);
    float*       hnext = g_h + (size_t)((t + 1) & 1) * (HID * NB);

    int lane = tid & 31, wid = tid >> 5;   // wid = kg (0..7), 16 k-rows each per chunk
    int mi = lane >> 2;                 // 0..7 -> m-pairs mi*4..mi*4+3  (m = mi*8..+7)
    int ci = lane & 3;                  // 0..3 -> cols ci*4..ci*4+3

    ull acc[16];
#pragma unroll
    for (int i = 0; i < 16; i++) acc[i] = 0;

    // register-prefetch staging: A 32 floats/thread, B 8 floats/thread per chunk
    float4 ra[8], rb[2];
#define LOAD_A(BASE)                                                             \
    _Pragma("unroll")                                                            \
    for (int i = 0; i < 8; i++) {                                                \
        int f = tid + i * 256; int row = f >> 4, pos = f & 15;                   \
        ra[i] = *(const float4*)&hprev[(size_t)((BASE) + row) * 64 + pos * 4];   \
    }
#define LOAD_B(BASE)                                                             \
    _Pragma("unroll")                                                            \
    for (int i = 0; i < 2; i++) {                                                \
        int f = tid + i * 256; int row = f >> 2, q = f & 3;                      \
        rb[i] = *(const float4*)&g_Wr[(size_t)((BASE) + row) * NC + C0 + q * 4]; \
    }

    LOAD_A(0)
    LOAD_B(0)

    for (int it = 0; it < 8; it++) {
        __syncthreads();
#pragma unroll
        for (int i = 0; i < 8; i++) {
            int f = tid + i * 256; int row = f >> 4, pos = f & 15;
            *(float4*)&ash[row * 64 + pos * 4] = ra[i];
        }
#pragma unroll
        for (int i = 0; i < 2; i++) {
            int f = tid + i * 256; int row = f >> 2, q = f & 3;
            *(float4*)&bsh[row * 16 + q * 4] = rb[i];
        }
        __syncthreads();
        if (it < 7) {
            int base = (it + 1) * 128;
            LOAD_A(base)
            LOAD_B(base)
        }
        const float* ap = &ash[(wid * 16) * 64 + mi * 8];
        const float* bp = &bsh[(wid * 16) * 16 + ci * 4];
#pragma unroll
        for (int kk = 0; kk < 16; kk++) {
            ulonglong2 a0 = *(const ulonglong2*)(ap + kk * 64);       // pairs p0,p1
            ulonglong2 a1 = *(const ulonglong2*)(ap + kk * 64 + 4);   // pairs p2,p3
            float4 bv = *(const float4*)(bp + kk * 16);               // cols c0..c3
            ull b0 = dup2(bv.x), b1 = dup2(bv.y), b2 = dup2(bv.z), b3 = dup2(bv.w);
            fma2(acc[0],  a0.x, b0); fma2(acc[1],  a0.x, b1);
            fma2(acc[2],  a0.x, b2); fma2(acc[3],  a0.x, b3);
            fma2(acc[4],  a0.y, b0); fma2(acc[5],  a0.y, b1);
            fma2(acc[6],  a0.y, b2); fma2(acc[7],  a0.y, b3);
            fma2(acc[8],  a1.x, b0); fma2(acc[9],  a1.x, b1);
            fma2(acc[10], a1.x, b2); fma2(acc[11], a1.x, b3);
            fma2(acc[12], a1.y, b0); fma2(acc[13], a1.y, b1);
            fma2(acc[14], a1.y, b2); fma2(acc[15], a1.y, b3);
        }
    }
#undef LOAD_A
#undef LOAD_B

    // split-K partials -> smem (alias ash region; 8 kg x 32 pairs x 16 cols = 32 KB)
    __syncthreads();
    ull* pu = (ull*)ash;
    {
        int pb = wid * 512;
#pragma unroll
        for (int p = 0; p < 4; p++)
#pragma unroll
            for (int c = 0; c < 4; c++)
                pu[pb + (mi * 4 + p) * 16 + ci * 4 + c] = acc[p * 4 + c];
    }
    __syncthreads();

    // gates: thread -> (m, jl):  m = tid>>2 (0..63), jl = tid&3
    int m  = tid >> 2;
    int jl = tid & 3;
    int P  = m >> 1, e = m & 1;

    float4 xp = *(const float4*)&g_xproj[((size_t)t * 64 + m) * NC + C0 + jl * 4];
    float pre[4];
#pragma unroll
    for (int g = 0; g < 4; g++) {
        int lc = P * 16 + jl * 4 + g;
        ull s = add2(add2(add2(pu[lc], pu[512 + lc]),
                          add2(pu[1024 + lc], pu[1536 + lc])),
                     add2(add2(pu[2048 + lc], pu[2560 + lc]),
                          add2(pu[3072 + lc], pu[3584 + lc])));
        float lo, hi; up2(s, lo, hi);
        pre[g] = e ? hi : lo;
    }
    pre[0] += xp.x; pre[1] += xp.y; pre[2] += xp.z; pre[3] += xp.w;

    float is = 1.f / (1.f + __expf(-pre[0]));
    float fs = 1.f / (1.f + __expf(-pre[1]));
    float gt = tanhf(pre[2]);
    float os = 1.f / (1.f + __expf(-pre[3]));

    int j = jb + jl;
    float cold = g_c[(size_t)j * 64 + m];
    float cn   = fs * cold + is * gt;
    g_c[(size_t)j * 64 + m]   = cn;
    float hv = os * tanhf(cn);
    hnext[(size_t)j * 64 + m] = hv;
    out[((size_t)t * 64 + m) * 1024 + j] = hv;
}

// ---------------- launcher ----------------
extern "C" void kernel_launch(void* const* d_in, const int* in_sizes, int n_in,
                              void* d_out, int out_size)
{
    const int*   x   = (const int*)  d_in[0];
    const float* emb = (const float*)d_in[1];
    const float* Wi  = (const float*)d_in[2];
    const float* bi  = (const float*)d_in[3];
    const float* Wf  = (const float*)d_in[4];
    const float* bf  = (const float*)d_in[5];
    const float* Wc  = (const float*)d_in[6];
    const float* bc  = (const float*)d_in[7];
    const float* Wo  = (const float*)d_in[8];
    const float* bo  = (const float*)d_in[9];
    float* out = (float*)d_out;
    (void)in_sizes; (void)n_in; (void)out_size;

    k_init<<<(HID * NB + 255) / 256, 256>>>();
    k_reorg<<<((HID + EMB) * HID + 255) / 256, 256>>>(Wi, bi, Wf, bf, Wc, bc, Wo, bo);

    dim3 g1(32, 512);
    k_embed_proj<<<g1, 256>>>(x, emb);

    for (int t = 0; t < L_SEQ; t++) {
        k_step<<<256, 256>>>(t, out);
    }
}

// round 7
// speedup vs baseline: 2.8760x; 1.2563x over previous
#include <cuda_runtime.h>
#include <cstdint>

#define L_SEQ 512
#define NB    64
#define HID   1024
#define EMB   512
#define NC    4096   // 4 gates * HID, interleaved col = j*4 + g  (g: 0=i,1=f,2=c,3=o)

typedef unsigned long long ull;

// ---------------- device scratch (no allocs allowed) ----------------
__device__ float g_xproj[(size_t)L_SEQ * NB * NC];     // 512 MB: bias + x-part preacts
__device__ float g_Wr[(size_t)(HID + EMB) * NC];       // 25 MB: interleaved weights
__device__ float g_br[NC];                             // interleaved bias
__device__ float g_h[2 * HID * NB];                    // ping-pong, layout [j][m]
__device__ float g_c[HID * NB];                        // layout [j][m]

// ---------------- packed fp32x2 helpers (FFMA2 on sm_103a) ----------------
__device__ __forceinline__ ull pk2(float a, float b) {
    ull r; asm("mov.b64 %0, {%1, %2};" : "=l"(r) : "f"(a), "f"(b)); return r;
}
__device__ __forceinline__ ull dup2(float v) {
    ull r; asm("mov.b64 %0, {%1, %1};" : "=l"(r) : "f"(v)); return r;
}
__device__ __forceinline__ void up2(ull v, float& lo, float& hi) {
    asm("mov.b64 {%0, %1}, %2;" : "=f"(lo), "=f"(hi) : "l"(v));
}
__device__ __forceinline__ void fma2(ull& d, ull a, ull b) {
    asm("fma.rn.f32x2 %0, %1, %2, %0;" : "+l"(d) : "l"(a), "l"(b));
}
__device__ __forceinline__ ull add2(ull a, ull b) {
    ull r; asm("add.rn.f32x2 %0, %1, %2;" : "=l"(r) : "l"(a), "l"(b)); return r;
}
__device__ __forceinline__ uint32_t su32(const void* p) {
    return (uint32_t)__cvta_generic_to_shared(p);
}
__device__ __forceinline__ void cpa16(uint32_t d, const float* g) {
    asm volatile("cp.async.cg.shared.global [%0], [%1], 16;" :: "r"(d), "l"(g));
}
#define CP_COMMIT() asm volatile("cp.async.commit_group;" ::: "memory")
#define CP_WAIT0()  asm volatile("cp.async.wait_group 0;" ::: "memory")

// ---------------- init: zero h0 (ping 0), c0 ----------------
__global__ void k_init() {
    int i = blockIdx.x * blockDim.x + threadIdx.x;
    if (i < HID * NB) { g_h[i] = 0.f; g_c[i] = 0.f; }
}

// ---------------- weight/bias reorg: col = j*4 + g ----------------
__global__ void k_reorg(const float* __restrict__ Wi, const float* __restrict__ bi,
                        const float* __restrict__ Wf, const float* __restrict__ bf,
                        const float* __restrict__ Wc, const float* __restrict__ bc,
                        const float* __restrict__ Wo, const float* __restrict__ bo) {
    int idx = blockIdx.x * 256 + threadIdx.x;
    if (idx < (HID + EMB) * HID) {
        int k = idx >> 10, j = idx & (HID - 1);
        size_t s = (size_t)k * HID + j;
        float4 v = make_float4(Wi[s], Wf[s], Wc[s], Wo[s]);
        *(float4*)&g_Wr[(size_t)k * NC + j * 4] = v;
    }
    if (idx < HID) {
        *(float4*)&g_br[idx * 4] = make_float4(bi[idx], bf[idx], bc[idx], bo[idx]);
    }
}

// ---------------- kernel 1: embedding gather + input projection ----------------
// xproj[m][c] = br[c] + sum_k emb[x[m]][k] * Wr[1024+k][c]
// grid: (16, 512) block 256.  CTA tile: 64 rows x 256 interleaved cols, K=512, KC=16.
// Thread tile: 4 m x 16 cols = 32 packed accumulators.
#define BPAD 20      // floats per 16-col group (16 data + 4 pad, 16B-aligned stride)
__global__ __launch_bounds__(256) void k_embed_proj(
    const int* __restrict__ x, const float* __restrict__ emb)
{
    __shared__ float a2[16][132];       // emb tile, duplicated pairs: [k][2m],[k][2m+1]
    __shared__ float bsh[16 * 16 * BPAD]; // W tile [k][group cg][16 + pad]

    int tid = threadIdx.x;
    int jb  = blockIdx.x * 256;      // col tile base (interleaved space)
    int by  = blockIdx.y;            // 64-row tile

    int arow  = tid & 63;
    int ahalf = tid >> 6;            // 0..3 -> k offset ahalf*4
    long tok  = x[by * 64 + arow];
    const float* erow = emb + (size_t)tok * EMB + ahalf * 4;

    int mg = tid >> 4;               // 0..15 -> m = mg*4
    int cg = tid & 15;               // 0..15 -> cols cg*16

    ull acc[32];
    {
        float4 b0 = *(const float4*)(g_br + jb + cg * 16);
        float4 b1 = *(const float4*)(g_br + jb + cg * 16 + 4);
        float4 b2 = *(const float4*)(g_br + jb + cg * 16 + 8);
        float4 b3 = *(const float4*)(g_br + jb + cg * 16 + 12);
        ull p[8] = { pk2(b0.x, b0.y), pk2(b0.z, b0.w), pk2(b1.x, b1.y), pk2(b1.z, b1.w),
                     pk2(b2.x, b2.y), pk2(b2.z, b2.w), pk2(b3.x, b3.y), pk2(b3.z, b3.w) };
#pragma unroll
        for (int m = 0; m < 4; m++)
#pragma unroll
            for (int q = 0; q < 8; q++) acc[m * 8 + q] = p[q];
    }

    // staging registers (prefetch distance 1)
    float4 va;
    float4 rb[4];
#define E_LOAD(KB)                                                               \
    va = *(const float4*)(erow + (KB));                                         \
    _Pragma("unroll")                                                            \
    for (int i_ = 0; i_ < 4; i_++) {                                             \
        int f_ = tid + i_ * 256; int r_ = f_ >> 6, q_ = f_ & 63;                 \
        rb[i_] = *(const float4*)&g_Wr[(size_t)(HID + (KB) + r_) * NC + jb + q_ * 4]; \
    }

    E_LOAD(0)

    for (int kb = 0; kb < EMB; kb += 16) {
        __syncthreads();
        {   // store A duplicated pairs
            int k0 = ahalf * 4;
            *(float2*)&a2[k0 + 0][2 * arow] = make_float2(va.x, va.x);
            *(float2*)&a2[k0 + 1][2 * arow] = make_float2(va.y, va.y);
            *(float2*)&a2[k0 + 2][2 * arow] = make_float2(va.z, va.z);
            *(float2*)&a2[k0 + 3][2 * arow] = make_float2(va.w, va.w);
        }
#pragma unroll
        for (int i_ = 0; i_ < 4; i_++) {   // store B (padded groups)
            int f_ = tid + i_ * 256; int r_ = f_ >> 6, q_ = f_ & 63;
            *(float4*)&bsh[r_ * (16 * BPAD) + (q_ >> 2) * BPAD + (q_ & 3) * 4] = rb[i_];
        }
        __syncthreads();
        if (kb + 16 < EMB) { E_LOAD(kb + 16) }

        const float* bp = &bsh[cg * BPAD];
#pragma unroll
        for (int k = 0; k < 16; k++) {
            ulonglong2 aa0 = *(const ulonglong2*)&a2[k][8 * mg];      // (m0,m0),(m1,m1)
            ulonglong2 aa1 = *(const ulonglong2*)&a2[k][8 * mg + 4];  // (m2,m2),(m3,m3)
            ulonglong2 bb0 = *(const ulonglong2*)(bp + k * (16 * BPAD));
            ulonglong2 bb1 = *(const ulonglong2*)(bp + k * (16 * BPAD) + 4);
            ulonglong2 bb2 = *(const ulonglong2*)(bp + k * (16 * BPAD) + 8);
            ulonglong2 bb3 = *(const ulonglong2*)(bp + k * (16 * BPAD) + 12);
            ull am[4] = { aa0.x, aa0.y, aa1.x, aa1.y };
            ull bq[8] = { bb0.x, bb0.y, bb1.x, bb1.y, bb2.x, bb2.y, bb3.x, bb3.y };
#pragma unroll
            for (int m = 0; m < 4; m++)
#pragma unroll
                for (int q = 0; q < 8; q++) fma2(acc[m * 8 + q], am[m], bq[q]);
        }
    }
#undef E_LOAD

#pragma unroll
    for (int m = 0; m < 4; m++) {
        float* op = g_xproj + (size_t)(by * 64 + mg * 4 + m) * NC + jb + cg * 16;
        float l0, h0, l1, h1;
#pragma unroll
        for (int q = 0; q < 4; q++) {
            up2(acc[m * 8 + 2 * q], l0, h0);
            up2(acc[m * 8 + 2 * q + 1], l1, h1);
            *(float4*)(op + q * 4) = make_float4(l0, h0, l1, h1);
        }
    }
}

// ---------------- kernel 2: one LSTM timestep (GEMM + gates fused) ----------------
// grid: 256 CTAs x 256 threads. CTA owns 4 hidden units (16 interleaved cols), 64 batch.
// 8 warps = 8-way split-K. cp.async double-buffered chunks of 64 k-rows.
// Thread: 4 m-pairs x 4 cols = 16 packed accumulators; per k: 3 LDS.128 + 16 FFMA2.
#define STG 5120   // floats per stage: A 64x64 (4096) + B 64x16 (1024)
__global__ __launch_bounds__(256, 2) void k_step(int t, float* __restrict__ out)
{
    __shared__ __align__(16) float sm[2 * STG];   // 40 KB; partials alias after loop

    int tid = threadIdx.x;
    int jb  = blockIdx.x * 4;           // hidden units jb..jb+3
    int C0  = jb * 4;                   // interleaved col base (16 cols)
    const float* hprev = g_h + (size_t)(t & 1) * (HID * NB);
    float*       hnext = g_h + (size_t)((t + 1) & 1) * (HID * NB);

    int lane = tid & 31, wid = tid >> 5;   // wid = split-K index (8 k-rows per chunk)
    int mi = lane >> 2;                 // 0..7 -> m-pairs mi*4..+3  (m = mi*8..+7)
    int ci = lane & 3;                  // 0..3 -> cols ci*4..+3

    ull acc[16];
#pragma unroll
    for (int i = 0; i < 16; i++) acc[i] = 0;

#define PF(S, BASE) do {                                                         \
    float* as_ = sm + (S) * STG;                                                 \
    _Pragma("unroll")                                                            \
    for (int i_ = 0; i_ < 4; i_++) {                                             \
        int f_ = tid + i_ * 256, r_ = f_ >> 4, p_ = f_ & 15;                     \
        cpa16(su32(as_ + r_ * 64 + p_ * 4),                                      \
              &hprev[(size_t)((BASE) + r_) * 64 + p_ * 4]);                      \
    }                                                                            \
    { int r_ = tid >> 2, q_ = tid & 3;                                           \
      cpa16(su32(as_ + 4096 + r_ * 16 + q_ * 4),                                 \
            &g_Wr[(size_t)((BASE) + r_) * NC + C0 + q_ * 4]); }                  \
    CP_COMMIT();                                                                 \
} while (0)

    PF(0, 0);

    for (int it = 0; it < 16; it++) {
        CP_WAIT0();
        __syncthreads();
        if (it < 15) PF((it + 1) & 1, (it + 1) * 64);
        const float* ap = sm + (it & 1) * STG + (wid * 8) * 64 + mi * 8;
        const float* bp = sm + (it & 1) * STG + 4096 + (wid * 8) * 16 + ci * 4;
#pragma unroll
        for (int kk = 0; kk < 8; kk++) {
            ulonglong2 a0 = *(const ulonglong2*)(ap + kk * 64);       // pairs p0,p1
            ulonglong2 a1 = *(const ulonglong2*)(ap + kk * 64 + 4);   // pairs p2,p3
            float4 bv = *(const float4*)(bp + kk * 16);               // cols c0..c3
            ull b0 = dup2(bv.x), b1 = dup2(bv.y), b2 = dup2(bv.z), b3 = dup2(bv.w);
            fma2(acc[0],  a0.x, b0); fma2(acc[1],  a0.x, b1);
            fma2(acc[2],  a0.x, b2); fma2(acc[3],  a0.x, b3);
            fma2(acc[4],  a0.y, b0); fma2(acc[5],  a0.y, b1);
            fma2(acc[6],  a0.y, b2); fma2(acc[7],  a0.y, b3);
            fma2(acc[8],  a1.x, b0); fma2(acc[9],  a1.x, b1);
            fma2(acc[10], a1.x, b2); fma2(acc[11], a1.x, b3);
            fma2(acc[12], a1.y, b0); fma2(acc[13], a1.y, b1);
            fma2(acc[14], a1.y, b2); fma2(acc[15], a1.y, b3);
        }
    }
#undef PF

    // split-K partials -> smem (alias stages; 8 kg x 32 pairs x 16 cols = 32 KB)
    __syncthreads();
    ull* pu = (ull*)sm;
    {
        int pb = wid * 512;
#pragma unroll
        for (int p = 0; p < 4; p++)
#pragma unroll
            for (int c = 0; c < 4; c++)
                pu[pb + (mi * 4 + p) * 16 + ci * 4 + c] = acc[p * 4 + c];
    }
    __syncthreads();

    // gates: thread -> (m, jl):  m = tid>>2 (0..63), jl = tid&3
    int m  = tid >> 2;
    int jl = tid & 3;
    int P  = m >> 1, e = m & 1;

    float4 xp = *(const float4*)&g_xproj[((size_t)t * 64 + m) * NC + C0 + jl * 4];
    float pre[4];
#pragma unroll
    for (int g = 0; g < 4; g++) {
        int lc = P * 16 + jl * 4 + g;
        ull s = add2(add2(add2(pu[lc], pu[512 + lc]),
                          add2(pu[1024 + lc], pu[1536 + lc])),
                     add2(add2(pu[2048 + lc], pu[2560 + lc]),
                          add2(pu[3072 + lc], pu[3584 + lc])));
        float lo, hi; up2(s, lo, hi);
        pre[g] = e ? hi : lo;
    }
    pre[0] += xp.x; pre[1] += xp.y; pre[2] += xp.z; pre[3] += xp.w;

    float is = 1.f / (1.f + __expf(-pre[0]));
    float fs = 1.f / (1.f + __expf(-pre[1]));
    float gt = tanhf(pre[2]);
    float os = 1.f / (1.f + __expf(-pre[3]));

    int j = jb + jl;
    float cold = g_c[(size_t)j * 64 + m];
    float cn   = fs * cold + is * gt;
    g_c[(size_t)j * 64 + m]   = cn;
    float hv = os * tanhf(cn);
    hnext[(size_t)j * 64 + m] = hv;
    out[((size_t)t * 64 + m) * 1024 + j] = hv;
}

// ---------------- launcher ----------------
extern "C" void kernel_launch(void* const* d_in, const int* in_sizes, int n_in,
                              void* d_out, int out_size)
{
    const int*   x   = (const int*)  d_in[0];
    const float* emb = (const float*)d_in[1];
    const float* Wi  = (const float*)d_in[2];
    const float* bi  = (const float*)d_in[3];
    const float* Wf  = (const float*)d_in[4];
    const float* bf  = (const float*)d_in[5];
    const float* Wc  = (const float*)d_in[6];
    const float* bc  = (const float*)d_in[7];
    const float* Wo  = (const float*)d_in[8];
    const float* bo  = (const float*)d_in[9];
    float* out = (float*)d_out;
    (void)in_sizes; (void)n_in; (void)out_size;

    k_init<<<(HID * NB + 255) / 256, 256>>>();
    k_reorg<<<((HID + EMB) * HID + 255) / 256, 256>>>(Wi, bi, Wf, bf, Wc, bc, Wo, bo);

    dim3 g1(16, 512);
    k_embed_proj<<<g1, 256>>>(x, emb);

    for (int t = 0; t < L_SEQ; t++) {
        k_step<<<256, 256>>>(t, out);
    }
}

// round 8
// speedup vs baseline: 2.9880x; 1.0389x over previous
#include <cuda_runtime.h>
#include <cstdint>

#define L_SEQ 512
#define NB    64
#define HID   1024
#define EMB   512
#define NC    4096   // 4 gates * HID, interleaved col = j*4 + g  (g: 0=i,1=f,2=c,3=o)
#define NCTAS 256    // persistent grid; 2 CTAs/SM on 128 SMs -> all resident

typedef unsigned long long ull;

// ---------------- device scratch (no allocs allowed) ----------------
__device__ float g_xproj[(size_t)L_SEQ * NB * NC];     // 512 MB: bias + x-part preacts
__device__ float g_Wr[(size_t)(HID + EMB) * NC];       // 25 MB: interleaved weights
__device__ float g_br[NC];                             // interleaved bias
__device__ float g_h[2 * HID * NB];                    // ping-pong, layout [j][m]
__device__ volatile unsigned g_bar;                    // grid barrier arrival counter

// ---------------- packed fp32x2 helpers (FFMA2 on sm_103a) ----------------
__device__ __forceinline__ ull pk2(float a, float b) {
    ull r; asm("mov.b64 %0, {%1, %2};" : "=l"(r) : "f"(a), "f"(b)); return r;
}
__device__ __forceinline__ ull dup2(float v) {
    ull r; asm("mov.b64 %0, {%1, %1};" : "=l"(r) : "f"(v)); return r;
}
__device__ __forceinline__ void up2(ull v, float& lo, float& hi) {
    asm("mov.b64 {%0, %1}, %2;" : "=f"(lo), "=f"(hi) : "l"(v));
}
__device__ __forceinline__ void fma2(ull& d, ull a, ull b) {
    asm("fma.rn.f32x2 %0, %1, %2, %0;" : "+l"(d) : "l"(a), "l"(b));
}
__device__ __forceinline__ ull add2(ull a, ull b) {
    ull r; asm("add.rn.f32x2 %0, %1, %2;" : "=l"(r) : "l"(a), "l"(b)); return r;
}
__device__ __forceinline__ uint32_t su32(const void* p) {
    return (uint32_t)__cvta_generic_to_shared(p);
}
__device__ __forceinline__ void cpa16(uint32_t d, const float* g) {
    asm volatile("cp.async.cg.shared.global [%0], [%1], 16;" :: "r"(d), "l"(g));
}
#define CP_COMMIT() asm volatile("cp.async.commit_group;" ::: "memory")
#define CP_WAIT0()  asm volatile("cp.async.wait_group 0;" ::: "memory")

// ---------------- init: zero h0 (ping 0) + barrier counter ----------------
__global__ void k_init() {
    int i = blockIdx.x * blockDim.x + threadIdx.x;
    if (i < HID * NB) g_h[i] = 0.f;
    if (i == 0) g_bar = 0;
}

// ---------------- weight/bias reorg: col = j*4 + g ----------------
__global__ void k_reorg(const float* __restrict__ Wi, const float* __restrict__ bi,
                        const float* __restrict__ Wf, const float* __restrict__ bf,
                        const float* __restrict__ Wc, const float* __restrict__ bc,
                        const float* __restrict__ Wo, const float* __restrict__ bo) {
    int idx = blockIdx.x * 256 + threadIdx.x;
    if (idx < (HID + EMB) * HID) {
        int k = idx >> 10, j = idx & (HID - 1);
        size_t s = (size_t)k * HID + j;
        float4 v = make_float4(Wi[s], Wf[s], Wc[s], Wo[s]);
        *(float4*)&g_Wr[(size_t)k * NC + j * 4] = v;
    }
    if (idx < HID) {
        *(float4*)&g_br[idx * 4] = make_float4(bi[idx], bf[idx], bc[idx], bo[idx]);
    }
}

// ---------------- kernel 1: embedding gather + input projection ----------------
// xproj[m][c] = br[c] + sum_k emb[x[m]][k] * Wr[1024+k][c]
// grid: (16, 512) block 256.  CTA tile: 64 rows x 256 interleaved cols, K=512, KC=16.
#define BPAD 20      // floats per 16-col group (16 data + 4 pad, 16B-aligned stride)
__global__ __launch_bounds__(256) void k_embed_proj(
    const int* __restrict__ x, const float* __restrict__ emb)
{
    __shared__ float a2[16][132];         // emb tile, duplicated pairs
    __shared__ float bsh[16 * 16 * BPAD]; // W tile [k][group cg][16 + pad]

    int tid = threadIdx.x;
    int jb  = blockIdx.x * 256;
    int by  = blockIdx.y;

    int arow  = tid & 63;
    int ahalf = tid >> 6;
    long tok  = x[by * 64 + arow];
    const float* erow = emb + (size_t)tok * EMB + ahalf * 4;

    int mg = tid >> 4;
    int cg = tid & 15;

    ull acc[32];
    {
        float4 b0 = *(const float4*)(g_br + jb + cg * 16);
        float4 b1 = *(const float4*)(g_br + jb + cg * 16 + 4);
        float4 b2 = *(const float4*)(g_br + jb + cg * 16 + 8);
        float4 b3 = *(const float4*)(g_br + jb + cg * 16 + 12);
        ull p[8] = { pk2(b0.x, b0.y), pk2(b0.z, b0.w), pk2(b1.x, b1.y), pk2(b1.z, b1.w),
                     pk2(b2.x, b2.y), pk2(b2.z, b2.w), pk2(b3.x, b3.y), pk2(b3.z, b3.w) };
#pragma unroll
        for (int m = 0; m < 4; m++)
#pragma unroll
            for (int q = 0; q < 8; q++) acc[m * 8 + q] = p[q];
    }

    float4 va;
    float4 rb[4];
#define E_LOAD(KB)                                                               \
    va = *(const float4*)(erow + (KB));                                         \
    _Pragma("unroll")                                                            \
    for (int i_ = 0; i_ < 4; i_++) {                                             \
        int f_ = tid + i_ * 256; int r_ = f_ >> 6, q_ = f_ & 63;                 \
        rb[i_] = *(const float4*)&g_Wr[(size_t)(HID + (KB) + r_) * NC + jb + q_ * 4]; \
    }

    E_LOAD(0)

    for (int kb = 0; kb < EMB; kb += 16) {
        __syncthreads();
        {
            int k0 = ahalf * 4;
            *(float2*)&a2[k0 + 0][2 * arow] = make_float2(va.x, va.x);
            *(float2*)&a2[k0 + 1][2 * arow] = make_float2(va.y, va.y);
            *(float2*)&a2[k0 + 2][2 * arow] = make_float2(va.z, va.z);
            *(float2*)&a2[k0 + 3][2 * arow] = make_float2(va.w, va.w);
        }
#pragma unroll
        for (int i_ = 0; i_ < 4; i_++) {
            int f_ = tid + i_ * 256; int r_ = f_ >> 6, q_ = f_ & 63;
            *(float4*)&bsh[r_ * (16 * BPAD) + (q_ >> 2) * BPAD + (q_ & 3) * 4] = rb[i_];
        }
        __syncthreads();
        if (kb + 16 < EMB) { E_LOAD(kb + 16) }

        const float* bp = &bsh[cg * BPAD];
#pragma unroll
        for (int k = 0; k < 16; k++) {
            ulonglong2 aa0 = *(const ulonglong2*)&a2[k][8 * mg];
            ulonglong2 aa1 = *(const ulonglong2*)&a2[k][8 * mg + 4];
            ulonglong2 bb0 = *(const ulonglong2*)(bp + k * (16 * BPAD));
            ulonglong2 bb1 = *(const ulonglong2*)(bp + k * (16 * BPAD) + 4);
            ulonglong2 bb2 = *(const ulonglong2*)(bp + k * (16 * BPAD) + 8);
            ulonglong2 bb3 = *(const ulonglong2*)(bp + k * (16 * BPAD) + 12);
            ull am[4] = { aa0.x, aa0.y, aa1.x, aa1.y };
            ull bq[8] = { bb0.x, bb0.y, bb1.x, bb1.y, bb2.x, bb2.y, bb3.x, bb3.y };
#pragma unroll
            for (int m = 0; m < 4; m++)
#pragma unroll
                for (int q = 0; q < 8; q++) fma2(acc[m * 8 + q], am[m], bq[q]);
        }
    }
#undef E_LOAD

#pragma unroll
    for (int m = 0; m < 4; m++) {
        float* op = g_xproj + (size_t)(by * 64 + mg * 4 + m) * NC + jb + cg * 16;
        float l0, h0, l1, h1;
#pragma unroll
        for (int q = 0; q < 4; q++) {
            up2(acc[m * 8 + 2 * q], l0, h0);
            up2(acc[m * 8 + 2 * q + 1], l1, h1);
            *(float4*)(op + q * 4) = make_float4(l0, h0, l1, h1);
        }
    }
}

// ---------------- kernel 2: PERSISTENT LSTM (all 512 steps, one launch) ---------
// 256 CTAs x 256 threads, 2 CTAs/SM (all resident -> software grid barrier safe).
// Per CTA: W slice (1024x16 = 64 KB) persistent in smem; h chunks cp.async
// double-buffered (2 x 16 KB); c state in registers; split-K-8 across warps.
#define W_FLOATS 16384          // 1024 x 16
#define STG_F    4096           // one stage: 64 k-rows x 64 m
#define SMEM_LSTM ((W_FLOATS + 2 * STG_F) * 4)   // 96 KB

__global__ __launch_bounds__(256, 2) void k_lstm(float* __restrict__ out)
{
    extern __shared__ __align__(16) float sm[];
    float* Wsm = sm;                 // [k 0..1023][16 cols]
    float* stg = sm + W_FLOATS;      // 2 stages x 4096 floats; partials alias

    int tid = threadIdx.x;
    int jb  = blockIdx.x * 4;        // hidden units jb..jb+3
    int C0  = jb * 4;                // interleaved col base (16 cols)

    // ---- load persistent W slice (16 float4 per thread, coalesced) ----
#pragma unroll
    for (int i = 0; i < 16; i++) {
        int f = tid + i * 256;       // float4 index 0..4095
        int r = f >> 2, q = f & 3;
        *(float4*)&Wsm[r * 16 + q * 4] =
            *(const float4*)&g_Wr[(size_t)r * NC + C0 + q * 4];
    }

    int lane = tid & 31, wid = tid >> 5;   // wid = split-K group (8 rows per chunk)
    int mi = lane >> 2;              // m-pairs mi*4..+3
    int ci = lane & 3;               // cols ci*4..+3
    int m  = tid >> 2;               // gate-phase batch row (fixed across steps)
    int jl = tid & 3;                // gate-phase hidden-unit lane
    int P  = m >> 1, e = m & 1;
    int j  = jb + jl;
    float c_reg = 0.f;               // cell state lives in a register

    __syncthreads();

#define PF(S, BASE, HP) do {                                                     \
    float* as_ = stg + (S) * STG_F;                                              \
    _Pragma("unroll")                                                            \
    for (int i_ = 0; i_ < 4; i_++) {                                             \
        int f_ = tid + i_ * 256, r_ = f_ >> 4, p_ = f_ & 15;                     \
        cpa16(su32(as_ + r_ * 64 + p_ * 4),                                      \
              (HP) + (size_t)((BASE) + r_) * 64 + p_ * 4);                       \
    }                                                                            \
    CP_COMMIT();                                                                 \
} while (0)

    for (int t = 0; t < L_SEQ; t++) {
        const float* hprev = g_h + (size_t)(t & 1) * (HID * NB);
        float*       hnext = g_h + (size_t)((t + 1) & 1) * (HID * NB);

        // issue x-part preact load early (consumed after GEMM)
        float4 xp = *(const float4*)&g_xproj[((size_t)t * 64 + m) * NC + C0 + jl * 4];

        ull acc[16];
#pragma unroll
        for (int i = 0; i < 16; i++) acc[i] = 0;

        PF(0, 0, hprev);

        for (int it = 0; it < 16; it++) {
            CP_WAIT0();
            __syncthreads();
            if (it < 15) PF((it + 1) & 1, (it + 1) * 64, hprev);
            const float* ap = stg + (it & 1) * STG_F + (wid * 8) * 64 + mi * 8;
            const float* bp = Wsm + (it * 64 + wid * 8) * 16 + ci * 4;
#pragma unroll
            for (int kk = 0; kk < 8; kk++) {
                ulonglong2 a0 = *(const ulonglong2*)(ap + kk * 64);
                ulonglong2 a1 = *(const ulonglong2*)(ap + kk * 64 + 4);
                float4 bv = *(const float4*)(bp + kk * 16);
                ull b0 = dup2(bv.x), b1 = dup2(bv.y), b2 = dup2(bv.z), b3 = dup2(bv.w);
                fma2(acc[0],  a0.x, b0); fma2(acc[1],  a0.x, b1);
                fma2(acc[2],  a0.x, b2); fma2(acc[3],  a0.x, b3);
                fma2(acc[4],  a0.y, b0); fma2(acc[5],  a0.y, b1);
                fma2(acc[6],  a0.y, b2); fma2(acc[7],  a0.y, b3);
                fma2(acc[8],  a1.x, b0); fma2(acc[9],  a1.x, b1);
                fma2(acc[10], a1.x, b2); fma2(acc[11], a1.x, b3);
                fma2(acc[12], a1.y, b0); fma2(acc[13], a1.y, b1);
                fma2(acc[14], a1.y, b2); fma2(acc[15], a1.y, b3);
            }
        }

        // split-K partials -> smem (alias both stages: 8 x 32 pairs x 16 cols ulls)
        __syncthreads();
        ull* pu = (ull*)stg;
        {
            int pb = wid * 512;
#pragma unroll
            for (int p = 0; p < 4; p++)
#pragma unroll
                for (int c = 0; c < 4; c++)
                    pu[pb + (mi * 4 + p) * 16 + ci * 4 + c] = acc[p * 4 + c];
        }
        __syncthreads();

        // gates
        float pre[4];
#pragma unroll
        for (int g = 0; g < 4; g++) {
            int lc = P * 16 + jl * 4 + g;
            ull s = add2(add2(add2(pu[lc], pu[512 + lc]),
                              add2(pu[1024 + lc], pu[1536 + lc])),
                         add2(add2(pu[2048 + lc], pu[2560 + lc]),
                              add2(pu[3072 + lc], pu[3584 + lc])));
            float lo, hi; up2(s, lo, hi);
            pre[g] = e ? hi : lo;
        }
        pre[0] += xp.x; pre[1] += xp.y; pre[2] += xp.z; pre[3] += xp.w;

        float is = 1.f / (1.f + __expf(-pre[0]));
        float fs = 1.f / (1.f + __expf(-pre[1]));
        float gt = tanhf(pre[2]);
        float os = 1.f / (1.f + __expf(-pre[3]));

        float cn = fs * c_reg + is * gt;
        c_reg = cn;
        float hv = os * tanhf(cn);
        hnext[(size_t)j * 64 + m] = hv;
        out[((size_t)t * 64 + m) * 1024 + j] = hv;

        // ---- software grid barrier (all 256 CTAs resident by occupancy) ----
        __threadfence();
        __syncthreads();
        if (tid == 0) {
            atomicAdd((unsigned*)&g_bar, 1u);
            unsigned target = (unsigned)(t + 1) * NCTAS;
            while (g_bar < target) { }
        }
        __syncthreads();
        __threadfence();
    }
#undef PF
}

// ---------------- launcher ----------------
extern "C" void kernel_launch(void* const* d_in, const int* in_sizes, int n_in,
                              void* d_out, int out_size)
{
    const int*   x   = (const int*)  d_in[0];
    const float* emb = (const float*)d_in[1];
    const float* Wi  = (const float*)d_in[2];
    const float* bi  = (const float*)d_in[3];
    const float* Wf  = (const float*)d_in[4];
    const float* bf  = (const float*)d_in[5];
    const float* Wc  = (const float*)d_in[6];
    const float* bc  = (const float*)d_in[7];
    const float* Wo  = (const float*)d_in[8];
    const float* bo  = (const float*)d_in[9];
    float* out = (float*)d_out;
    (void)in_sizes; (void)n_in; (void)out_size;

    static bool attr_done = false;
    if (!attr_done) {
        cudaFuncSetAttribute(k_lstm, cudaFuncAttributeMaxDynamicSharedMemorySize,
                             SMEM_LSTM);
        attr_done = true;
    }

    k_init<<<(HID * NB + 255) / 256, 256>>>();
    k_reorg<<<((HID + EMB) * HID + 255) / 256, 256>>>(Wi, bi, Wf, bf, Wc, bc, Wo, bo);

    dim3 g1(16, 512);
    k_embed_proj<<<g1, 256>>>(x, emb);

    k_lstm<<<NCTAS, 256, SMEM_LSTM>>>(out);
}